// round 8
// baseline (speedup 1.0000x reference)
#include <cuda_runtime.h>
#include <math.h>
#include <stdint.h>

// ---------------------------------------------------------------------------
// GRU: T=512, B=1024, H=128.  out = h_T @ w_out^T + b_out
//
// f32x2 (FFMA2) with the SIMD lane over K-PAIRS:
//   acc64 holds (sum over even k, sum over odd k); both operands of every
//   ffma2 come straight from shared memory via ld.shared.v2.u64 — no packing.
//
// Phase 1: persistent 148 CTAs x 512 threads (4 warps/SMSP), weights in smem
//          once per SM, 32-row input tiles double-buffered via registers.
// Phase 2: 128 CTAs x 256 threads (2 warps/SMSP), w_hh + h in smem,
//          xg prefetched one step ahead, biases folded into acc init.
// ---------------------------------------------------------------------------

typedef unsigned long long u64;

static __device__ __forceinline__ u64 pack2(float lo, float hi) {
    u64 r; asm("mov.b64 %0, {%1, %2};" : "=l"(r) : "f"(lo), "f"(hi)); return r;
}
static __device__ __forceinline__ void unpack2(u64 v, float& lo, float& hi) {
    asm("mov.b64 {%0, %1}, %2;" : "=f"(lo), "=f"(hi) : "l"(v));
}
static __device__ __forceinline__ u64 ffma2(u64 a, u64 b, u64 c) {
    u64 d; asm("fma.rn.f32x2 %0, %1, %2, %3;" : "=l"(d) : "l"(a), "l"(b), "l"(c)); return d;
}
static __device__ __forceinline__ void lds_v2u64(u64& a, u64& b, uint32_t addr) {
    asm volatile("ld.shared.v2.u64 {%0, %1}, [%2];" : "=l"(a), "=l"(b) : "r"(addr));
}
static __device__ __forceinline__ uint32_t smem_u32(const void* p) {
    uint32_t a;
    asm("{ .reg .u64 t; cvta.to.shared.u64 t, %1; cvt.u32.u64 %0, t; }" : "=r"(a) : "l"(p));
    return a;
}
static __device__ __forceinline__ float sigf(float x) {
    return __fdividef(1.0f, 1.0f + __expf(-x));
}
static __device__ __forceinline__ float tanhf_fast(float x) {
    float ax = fabsf(x);
    float e  = __expf(-2.0f * ax);
    float t  = __fdividef(1.0f - e, 1.0f + e);
    return copysignf(t, x);
}

constexpr int H  = 128;
constexpr int G  = 384;    // 3*H
constexpr int TT = 512;
constexpr int BB = 1024;

// precomputed input gates: [T*B][3H]  (~805 MB static device scratch)
__device__ float g_xg[(size_t)TT * BB * G];

// shared weight tile: ws4[kk][g] (kk = k/4, 4 k-values per float4), 32*384*16 B
constexpr int WS_BYTES = 32 * G * 16;      // 196608
constexpr int XS_PITCH = 132;              // float pitch per row (16B-aligned, low-conflict)

// ---------------------------------------------------------------------------
// Phase 1: g_xg = input @ w_ih^T + b_ih   (persistent GEMM)
// ---------------------------------------------------------------------------
constexpr int ROWS1 = 32;
constexpr int THR1  = 512;
constexpr int NBLK1 = (TT * BB) / ROWS1;   // 16384 tiles
constexpr int GRID1 = 148;
constexpr int SMEM1 = WS_BYTES + ROWS1 * XS_PITCH * 4;   // 213504 B

__global__ void __launch_bounds__(THR1) xg_kernel(const float* __restrict__ input,
                                                  const float* __restrict__ w_ih,
                                                  const float* __restrict__ b_ih) {
    extern __shared__ char smem[];
    float4* ws4 = (float4*)smem;
    float*  xs  = (float*)(smem + WS_BYTES);
    const uint32_t ws_a = smem_u32(smem);
    const uint32_t xs_a = ws_a + WS_BYTES;

    const int tid = threadIdx.x;
    const int u   = tid & 127;      // gate unit (gates u, u+128, u+256)
    const int s   = tid >> 7;       // row octet: rows s*8 .. s*8+7

    // stage weights once: ws4[kk*384 + g] = w_ih[g][4kk..4kk+3]
    const float4* w4 = (const float4*)w_ih;
    for (int i = tid; i < G * 32; i += THR1) {
        int g = i >> 5, kk = i & 31;
        ws4[kk * G + g] = w4[g * 32 + kk];
    }
    const float br = b_ih[u], bz = b_ih[u + 128], bn = b_ih[u + 256];

    const int r_st = tid >> 5, kq = tid & 31;   // staging map
    int j = blockIdx.x;
    float4 pf0, pf1;
    if (j < NBLK1) {
        const float4* in4 = (const float4*)(input + (size_t)j * ROWS1 * H);
        pf0 = in4[tid]; pf1 = in4[tid + THR1];
    }

    const uint32_t wb = ws_a + u * 16;
    const uint32_t xb = xs_a + (s * 8) * (XS_PITCH * 4);

    for (; j < NBLK1; j += GRID1) {
        __syncthreads();   // previous tile's readers done
        *(float4*)(xs + r_st * XS_PITCH + kq * 4)        = pf0;
        *(float4*)(xs + (r_st + 16) * XS_PITCH + kq * 4) = pf1;
        __syncthreads();   // tile visible

        int jn = j + GRID1;
        if (jn < NBLK1) {   // prefetch next tile (hides DRAM under compute)
            const float4* in4 = (const float4*)(input + (size_t)jn * ROWS1 * H);
            pf0 = in4[tid]; pf1 = in4[tid + THR1];
        }

        u64 aR[8], aZ[8], aN[8];
        #pragma unroll
        for (int r = 0; r < 8; r++) {
            aR[r] = pack2(br, 0.f); aZ[r] = pack2(bz, 0.f); aN[r] = pack2(bn, 0.f);
        }

        #pragma unroll 2
        for (int kk = 0; kk < 32; kk++) {
            u64 wr0, wr1, wz0, wz1, wn0, wn1;
            const uint32_t wo = wb + kk * (G * 16);
            lds_v2u64(wr0, wr1, wo);
            lds_v2u64(wz0, wz1, wo + 128 * 16);
            lds_v2u64(wn0, wn1, wo + 256 * 16);
            #pragma unroll
            for (int r = 0; r < 8; r++) {
                u64 x0, x1;
                lds_v2u64(x0, x1, xb + r * (XS_PITCH * 4) + kk * 16);   // broadcast
                aR[r] = ffma2(x0, wr0, aR[r]); aR[r] = ffma2(x1, wr1, aR[r]);
                aZ[r] = ffma2(x0, wz0, aZ[r]); aZ[r] = ffma2(x1, wz1, aZ[r]);
                aN[r] = ffma2(x0, wn0, aN[r]); aN[r] = ffma2(x1, wn1, aN[r]);
            }
        }

        float* outp = g_xg + ((size_t)j * ROWS1 + s * 8) * G + u;
        #pragma unroll
        for (int r = 0; r < 8; r++) {
            float l, h2;
            unpack2(aR[r], l, h2); outp[(size_t)r * G]       = l + h2;
            unpack2(aZ[r], l, h2); outp[(size_t)r * G + 128] = l + h2;
            unpack2(aN[r], l, h2); outp[(size_t)r * G + 256] = l + h2;
        }
    }
}

// ---------------------------------------------------------------------------
// Phase 2: sequential recurrence + output projection.
// 128 CTAs x 256 threads; thread (u, s) owns unit u for rows s*4..s*4+3.
// ---------------------------------------------------------------------------
constexpr int THR2  = 256;
constexpr int SMEM2 = WS_BYTES + 8 * XS_PITCH * 4 + 8 * H * 4;   // 204928 B

__global__ void __launch_bounds__(THR2) gru_kernel(const float* __restrict__ initial_h,
                                                   const float* __restrict__ w_hh,
                                                   const float* __restrict__ b_hh,
                                                   const float* __restrict__ w_out,
                                                   const float* __restrict__ b_out,
                                                   float* __restrict__ out) {
    extern __shared__ char smem[];
    float4* ws4 = (float4*)smem;
    float*  hs  = (float*)(smem + WS_BYTES);                       // [8][132]
    float*  red = (float*)(smem + WS_BYTES + 8 * XS_PITCH * 4);    // [8][128]
    const uint32_t ws_a = smem_u32(smem);
    const uint32_t hs_a = ws_a + WS_BYTES;

    const int tid = threadIdx.x;
    const int u   = tid & 127;
    const int s   = tid >> 7;          // 0: rows 0-3, 1: rows 4-7
    const int b0  = blockIdx.x * 8;

    const float4* w4 = (const float4*)w_hh;
    for (int i = tid; i < G * 32; i += THR2) {
        int g = i >> 5, kk = i & 31;
        ws4[kk * G + g] = w4[g * 32 + kk];
    }
    const float br = b_hh[u], bz = b_hh[u + 128], bn = b_hh[u + 256];

    float hreg[4];
    #pragma unroll
    for (int r = 0; r < 4; r++) {
        int row = s * 4 + r;
        hreg[r] = initial_h[(size_t)(b0 + row) * H + u];
        hs[row * XS_PITCH + u] = hreg[r];
    }

    // prefetch xg for t = 0
    float cxR[4], cxZ[4], cxN[4];
    {
        const float* xg0 = g_xg + ((size_t)0 * BB + b0) * G + u;
        #pragma unroll
        for (int r = 0; r < 4; r++) {
            int row = s * 4 + r;
            cxR[r] = xg0[(size_t)row * G];
            cxZ[r] = xg0[(size_t)row * G + 128];
            cxN[r] = xg0[(size_t)row * G + 256];
        }
    }
    __syncthreads();

    const uint32_t wb = ws_a + u * 16;
    const uint32_t hb = hs_a + (s * 4) * (XS_PITCH * 4);

    for (int t = 0; t < TT; t++) {
        // prefetch next step's xg (clamped; hides DRAM stream)
        float nxR[4], nxZ[4], nxN[4];
        {
            int tn = (t + 1 < TT) ? (t + 1) : t;
            const float* xgn = g_xg + ((size_t)tn * BB + b0) * G + u;
            #pragma unroll
            for (int r = 0; r < 4; r++) {
                int row = s * 4 + r;
                nxR[r] = xgn[(size_t)row * G];
                nxZ[r] = xgn[(size_t)row * G + 128];
                nxN[r] = xgn[(size_t)row * G + 256];
            }
        }

        u64 aR[4], aZ[4], aN[4];
        #pragma unroll
        for (int r = 0; r < 4; r++) {
            aR[r] = pack2(cxR[r] + br, 0.f);   // fold x + bias into acc init
            aZ[r] = pack2(cxZ[r] + bz, 0.f);
            aN[r] = pack2(bn, 0.f);            // n gate: r * (h@Wn + bn) — keep separate
        }

        #pragma unroll 2
        for (int kk = 0; kk < 32; kk++) {
            u64 wr0, wr1, wz0, wz1, wn0, wn1;
            const uint32_t wo = wb + kk * (G * 16);
            lds_v2u64(wr0, wr1, wo);
            lds_v2u64(wz0, wz1, wo + 128 * 16);
            lds_v2u64(wn0, wn1, wo + 256 * 16);
            #pragma unroll
            for (int r = 0; r < 4; r++) {
                u64 x0, x1;
                lds_v2u64(x0, x1, hb + r * (XS_PITCH * 4) + kk * 16);   // broadcast
                aR[r] = ffma2(x0, wr0, aR[r]); aR[r] = ffma2(x1, wr1, aR[r]);
                aZ[r] = ffma2(x0, wz0, aZ[r]); aZ[r] = ffma2(x1, wz1, aZ[r]);
                aN[r] = ffma2(x0, wn0, aN[r]); aN[r] = ffma2(x1, wn1, aN[r]);
            }
        }

        // gates + state update (thread-local, no cross-thread comm)
        #pragma unroll
        for (int r = 0; r < 4; r++) {
            float l, h2;
            unpack2(aR[r], l, h2); float rg = sigf(l + h2);
            unpack2(aZ[r], l, h2); float zg = sigf(l + h2);
            unpack2(aN[r], l, h2); float ng = tanhf_fast(cxN[r] + rg * (l + h2));
            hreg[r] = (1.0f - zg) * ng + zg * hreg[r];
            cxR[r] = nxR[r]; cxZ[r] = nxZ[r]; cxN[r] = nxN[r];
        }

        __syncthreads();   // all matvec reads of hs done
        #pragma unroll
        for (int r = 0; r < 4; r++) hs[(s * 4 + r) * XS_PITCH + u] = hreg[r];
        __syncthreads();   // new h visible
    }

    // projection: out[b] = sum_u h[b][u]*w_out[u] + b_out (deterministic tree)
    const float wo = w_out[u];
    #pragma unroll
    for (int r = 0; r < 4; r++) red[(s * 4 + r) * H + u] = hreg[r] * wo;
    __syncthreads();
    for (int st = 64; st > 0; st >>= 1) {
        if (u < st) {
            #pragma unroll
            for (int r = 0; r < 4; r++)
                red[(s * 4 + r) * H + u] += red[(s * 4 + r) * H + u + st];
        }
        __syncthreads();
    }
    if (tid < 8) out[b0 + tid] = red[tid * H] + b_out[0];
}

// ---------------------------------------------------------------------------
// launch
// ---------------------------------------------------------------------------
extern "C" void kernel_launch(void* const* d_in, const int* in_sizes, int n_in,
                              void* d_out, int out_size) {
    const float* input     = (const float*)d_in[0];   // [T, B, H]
    const float* initial_h = (const float*)d_in[1];   // [B, H]
    const float* w_ih      = (const float*)d_in[2];   // [3H, H]
    const float* w_hh      = (const float*)d_in[3];   // [3H, H]
    const float* b_ih      = (const float*)d_in[4];   // [3H]
    const float* b_hh      = (const float*)d_in[5];   // [3H]
    const float* w_out     = (const float*)d_in[6];   // [1, H]
    const float* b_out     = (const float*)d_in[7];   // [1]
    float*       out       = (float*)d_out;           // [B, 1]

    (void)in_sizes; (void)n_in; (void)out_size;

    cudaFuncSetAttribute(xg_kernel,  cudaFuncAttributeMaxDynamicSharedMemorySize, SMEM1);
    cudaFuncSetAttribute(gru_kernel, cudaFuncAttributeMaxDynamicSharedMemorySize, SMEM2);

    xg_kernel<<<GRID1, THR1, SMEM1>>>(input, w_ih, b_ih);
    gru_kernel<<<BB / 8, THR2, SMEM2>>>(initial_h, w_hh, b_hh, w_out, b_out, out);
}

// round 9
// speedup vs baseline: 1.1552x; 1.1552x over previous
#include <cuda_runtime.h>
#include <math.h>
#include <stdint.h>

// ---------------------------------------------------------------------------
// GRU: T=512, B=1024, H=128.  out = h_T @ w_out^T + b_out
//
// Phase 1: persistent GEMM, cp.async double-buffered input tiles, FFMA2.
// Phase 2: recurrence with SPLIT-K: 128 units x 2 k-halves per CTA.
//          Every w_hh byte crosses the smem crossbar exactly once per SM per
//          step (no per-warp duplication) -> fma-bound inner loop.
//          Partial sums exchanged through smem once per step (12KB).
// ---------------------------------------------------------------------------

typedef unsigned long long u64;

static __device__ __forceinline__ u64 pack2(float lo, float hi) {
    u64 r; asm("mov.b64 %0, {%1, %2};" : "=l"(r) : "f"(lo), "f"(hi)); return r;
}
static __device__ __forceinline__ void unpack2(u64 v, float& lo, float& hi) {
    asm("mov.b64 {%0, %1}, %2;" : "=f"(lo), "=f"(hi) : "l"(v));
}
static __device__ __forceinline__ u64 ffma2(u64 a, u64 b, u64 c) {
    u64 d; asm("fma.rn.f32x2 %0, %1, %2, %3;" : "=l"(d) : "l"(a), "l"(b), "l"(c)); return d;
}
static __device__ __forceinline__ void lds_v2u64(u64& a, u64& b, uint32_t addr) {
    asm volatile("ld.shared.v2.u64 {%0, %1}, [%2];" : "=l"(a), "=l"(b) : "r"(addr));
}
static __device__ __forceinline__ uint32_t smem_u32(const void* p) {
    uint32_t a;
    asm("{ .reg .u64 t; cvta.to.shared.u64 t, %1; cvt.u32.u64 %0, t; }" : "=r"(a) : "l"(p));
    return a;
}
static __device__ __forceinline__ void cp16(uint32_t dst, const void* src) {
    asm volatile("cp.async.cg.shared.global [%0], [%1], 16;" :: "r"(dst), "l"(src));
}
static __device__ __forceinline__ void cp_commit() {
    asm volatile("cp.async.commit_group;");
}
static __device__ __forceinline__ void cp_wait1() {
    asm volatile("cp.async.wait_group 1;");
}
static __device__ __forceinline__ void cp_wait0() {
    asm volatile("cp.async.wait_group 0;");
}
static __device__ __forceinline__ float sigf(float x) {
    return __fdividef(1.0f, 1.0f + __expf(-x));
}
static __device__ __forceinline__ float tanhf_fast(float x) {
    float ax = fabsf(x);
    float e  = __expf(-2.0f * ax);
    float t  = __fdividef(1.0f - e, 1.0f + e);
    return copysignf(t, x);
}

constexpr int H  = 128;
constexpr int G  = 384;    // 3*H
constexpr int TT = 512;
constexpr int BB = 1024;

// precomputed input gates: [T*B][3H]  (~805 MB static device scratch)
__device__ float g_xg[(size_t)TT * BB * G];

// shared weight tile: ws4[kk][g] (kk = k/4), 32*384*16 B
constexpr int WS_BYTES = 32 * G * 16;      // 196608
constexpr int RP       = 528;              // row pitch in BYTES (132 floats)

// ---------------------------------------------------------------------------
// Phase 1: g_xg = input @ w_ih^T + b_ih   (persistent GEMM, cp.async staging)
// ---------------------------------------------------------------------------
constexpr int ROWS1    = 32;
constexpr int THR1     = 512;
constexpr int NBLK1    = (TT * BB) / ROWS1;   // 16384 tiles
constexpr int GRID1    = 148;
constexpr int XS_BYTES = ROWS1 * RP;          // 16896
constexpr int SMEM1    = WS_BYTES + 2 * XS_BYTES;   // 230400

__global__ void __launch_bounds__(THR1) xg_kernel(const float* __restrict__ input,
                                                  const float* __restrict__ w_ih,
                                                  const float* __restrict__ b_ih) {
    extern __shared__ char smem[];
    float4* ws4 = (float4*)smem;
    const uint32_t ws_a = smem_u32(smem);
    const uint32_t xs_a = ws_a + WS_BYTES;

    const int tid = threadIdx.x;
    const int u   = tid & 127;      // gate unit (gates u, u+128, u+256)
    const int s   = tid >> 7;       // row octet: rows s*8 .. s*8+7

    // stage tile 0 / tile 1 via cp.async while we also stage weights
    const int i0 = tid, i1 = tid + THR1;
    const uint32_t d0 = xs_a + (i0 >> 5) * RP + (i0 & 31) * 16;
    const uint32_t d1 = xs_a + (i1 >> 5) * RP + (i1 & 31) * 16;
    {
        const float4* in4 = (const float4*)(input + (size_t)blockIdx.x * ROWS1 * H);
        cp16(d0, in4 + i0); cp16(d1, in4 + i1); cp_commit();
        const float4* in4b = (const float4*)(input + (size_t)(blockIdx.x + GRID1) * ROWS1 * H);
        cp16(d0 + XS_BYTES, in4b + i0); cp16(d1 + XS_BYTES, in4b + i1); cp_commit();
    }

    // stage weights once: ws4[kk*384 + g] = w_ih[g][4kk..4kk+3]
    const float4* w4 = (const float4*)w_ih;
    for (int i = tid; i < G * 32; i += THR1) {
        int g = i >> 5, kk = i & 31;
        ws4[kk * G + g] = w4[g * 32 + kk];
    }
    const float br = b_ih[u], bz = b_ih[u + 128], bn = b_ih[u + 256];

    const uint32_t wb = ws_a + u * 16;
    int p = 0;

    for (int j = blockIdx.x; j < NBLK1; j += GRID1) {
        cp_wait1();          // buffer p filled
        __syncthreads();     // visible to all (also covers weight staging, 1st iter)

        const uint32_t xb = xs_a + p * XS_BYTES + (s * 8) * RP;

        u64 aR[8], aZ[8], aN[8];
        #pragma unroll
        for (int r = 0; r < 8; r++) {
            aR[r] = pack2(br, 0.f); aZ[r] = pack2(bz, 0.f); aN[r] = pack2(bn, 0.f);
        }

        #pragma unroll 2
        for (int kk = 0; kk < 32; kk++) {
            u64 wr0, wr1, wz0, wz1, wn0, wn1;
            const uint32_t wo = wb + kk * (G * 16);
            lds_v2u64(wr0, wr1, wo);
            lds_v2u64(wz0, wz1, wo + 128 * 16);
            lds_v2u64(wn0, wn1, wo + 256 * 16);
            #pragma unroll
            for (int r = 0; r < 8; r++) {
                u64 x0, x1;
                lds_v2u64(x0, x1, xb + r * RP + kk * 16);   // broadcast
                aR[r] = ffma2(x0, wr0, aR[r]); aR[r] = ffma2(x1, wr1, aR[r]);
                aZ[r] = ffma2(x0, wz0, aZ[r]); aZ[r] = ffma2(x1, wz1, aZ[r]);
                aN[r] = ffma2(x0, wn0, aN[r]); aN[r] = ffma2(x1, wn1, aN[r]);
            }
        }

        float* outp = g_xg + ((size_t)j * ROWS1 + s * 8) * G + u;
        #pragma unroll
        for (int r = 0; r < 8; r++) {
            float l, h2;
            unpack2(aR[r], l, h2); outp[(size_t)r * G]       = l + h2;
            unpack2(aZ[r], l, h2); outp[(size_t)r * G + 128] = l + h2;
            unpack2(aN[r], l, h2); outp[(size_t)r * G + 256] = l + h2;
        }

        __syncthreads();     // everyone done reading buffer p
        int jn = j + 2 * GRID1;
        if (jn < NBLK1) {    // refill buffer p
            const float4* in4 = (const float4*)(input + (size_t)jn * ROWS1 * H);
            cp16(xs_a + p * XS_BYTES + (i0 >> 5) * RP + (i0 & 31) * 16, in4 + i0);
            cp16(xs_a + p * XS_BYTES + (i1 >> 5) * RP + (i1 & 31) * 16, in4 + i1);
        }
        cp_commit();         // commit even if empty (keeps wait accounting)
        p ^= 1;
    }
    cp_wait0();
}

// ---------------------------------------------------------------------------
// Phase 2: split-K recurrence. 128 CTAs x 256 threads.
// thread (u, kh): partial hg over k in [64kh, 64kh+64) for all 8 rows;
// gates + h update for rows [4kh, 4kh+4).
// ---------------------------------------------------------------------------
constexpr int THR2   = 256;
constexpr int HSB    = 8 * RP;                 // 4224 per h buffer
constexpr int PXSIDE = 4 * 3 * 128 * 4;        // 6144 per exchange side
constexpr int SMEM2  = WS_BYTES + 2 * HSB + 2 * PXSIDE + 8 * H * 4;  // 221440

__global__ void __launch_bounds__(THR2) gru_kernel(const float* __restrict__ initial_h,
                                                   const float* __restrict__ w_hh,
                                                   const float* __restrict__ b_hh,
                                                   const float* __restrict__ w_out,
                                                   const float* __restrict__ b_out,
                                                   float* __restrict__ out) {
    extern __shared__ char smem[];
    float4* ws4 = (float4*)smem;
    float*  hsf = (float*)(smem + WS_BYTES);                         // 2 x [8][132]
    float*  pxf = (float*)(smem + WS_BYTES + 2 * HSB);               // 2 x [4][3][128]
    float*  red = (float*)(smem + WS_BYTES + 2 * HSB + 2 * PXSIDE);  // [8][128]
    const uint32_t ws_a = smem_u32(smem);
    const uint32_t hs_a = ws_a + WS_BYTES;

    const int tid = threadIdx.x;
    const int u   = tid & 127;
    const int kh  = tid >> 7;          // k-half
    const int r0  = kh * 4;            // own gate rows: r0 .. r0+3
    const int b0  = blockIdx.x * 8;

    const float4* w4 = (const float4*)w_hh;
    for (int i = tid; i < G * 32; i += THR2) {
        int g = i >> 5, kk = i & 31;
        ws4[kk * G + g] = w4[g * 32 + kk];
    }
    const float br = b_hh[u], bz = b_hh[u + 128], bn = b_hh[u + 256];

    // init h (each half writes its own 4 rows; both halves cover 8)
    float hreg[4];
    #pragma unroll
    for (int i = 0; i < 4; i++) {
        hreg[i] = initial_h[(size_t)(b0 + r0 + i) * H + u];
        hsf[(r0 + i) * 132 + u] = hreg[i];
    }

    // prefetch xg for t = 0 (own rows only)
    float cxR[4], cxZ[4], cxN[4];
    {
        const float* xg0 = g_xg + ((size_t)b0 + r0) * G + u;
        #pragma unroll
        for (int i = 0; i < 4; i++) {
            cxR[i] = xg0[(size_t)i * G];
            cxZ[i] = xg0[(size_t)i * G + 128];
            cxN[i] = xg0[(size_t)i * G + 256];
        }
    }
    __syncthreads();

    // weight base for this (u, k-half); h base includes the k-half byte offset
    const uint32_t wb = ws_a + u * 16 + kh * 16 * (G * 16);
    const int     ro  = 4 - r0;          // other half's first row
    float* pxw = pxf + kh * (4 * 3 * 128) + u;         // write side (our partials)
    float* pxr = pxf + (1 - kh) * (4 * 3 * 128) + u;   // read side (partner's)

    int p = 0;
    for (int t = 0; t < TT; t++) {
        // prefetch next step's xg (own rows)
        float nxR[4], nxZ[4], nxN[4];
        {
            int tn = (t + 1 < TT) ? (t + 1) : t;
            const float* xgn = g_xg + ((size_t)tn * BB + b0 + r0) * G + u;
            #pragma unroll
            for (int i = 0; i < 4; i++) {
                nxR[i] = xgn[(size_t)i * G];
                nxZ[i] = xgn[(size_t)i * G + 128];
                nxN[i] = xgn[(size_t)i * G + 256];
            }
        }

        // accumulators: [0..3] own rows (x+bias folded), [4..7] other rows
        u64 aR[8], aZ[8], aN[8];
        #pragma unroll
        for (int i = 0; i < 4; i++) {
            aR[i] = pack2(cxR[i] + br, 0.f);
            aZ[i] = pack2(cxZ[i] + bz, 0.f);
            aN[i] = pack2(bn, 0.f);
            aR[4 + i] = 0; aZ[4 + i] = 0; aN[4 + i] = 0;
        }

        const uint32_t hb_own = hs_a + p * HSB + r0 * RP + kh * 256;
        const uint32_t hb_oth = hs_a + p * HSB + ro * RP + kh * 256;

        #pragma unroll 2
        for (int kk = 0; kk < 16; kk++) {
            u64 wr0, wr1, wz0, wz1, wn0, wn1;
            const uint32_t wo = wb + kk * (G * 16);
            lds_v2u64(wr0, wr1, wo);
            lds_v2u64(wz0, wz1, wo + 128 * 16);
            lds_v2u64(wn0, wn1, wo + 256 * 16);
            #pragma unroll
            for (int i = 0; i < 4; i++) {
                u64 x0, x1;
                lds_v2u64(x0, x1, hb_own + i * RP + kk * 16);   // broadcast
                aR[i] = ffma2(x0, wr0, aR[i]); aR[i] = ffma2(x1, wr1, aR[i]);
                aZ[i] = ffma2(x0, wz0, aZ[i]); aZ[i] = ffma2(x1, wz1, aZ[i]);
                aN[i] = ffma2(x0, wn0, aN[i]); aN[i] = ffma2(x1, wn1, aN[i]);
            }
            #pragma unroll
            for (int i = 0; i < 4; i++) {
                u64 x0, x1;
                lds_v2u64(x0, x1, hb_oth + i * RP + kk * 16);   // broadcast
                aR[4+i] = ffma2(x0, wr0, aR[4+i]); aR[4+i] = ffma2(x1, wr1, aR[4+i]);
                aZ[4+i] = ffma2(x0, wz0, aZ[4+i]); aZ[4+i] = ffma2(x1, wz1, aZ[4+i]);
                aN[4+i] = ffma2(x0, wn0, aN[4+i]); aN[4+i] = ffma2(x1, wn1, aN[4+i]);
            }
        }

        // fold own sums; export other-rows partials
        float sR[4], sZ[4], sN[4];
        #pragma unroll
        for (int i = 0; i < 4; i++) {
            float l, h2;
            unpack2(aR[i], l, h2); sR[i] = l + h2;
            unpack2(aZ[i], l, h2); sZ[i] = l + h2;
            unpack2(aN[i], l, h2); sN[i] = l + h2;
            unpack2(aR[4+i], l, h2); pxw[i * 384 + 0  ] = l + h2;
            unpack2(aZ[4+i], l, h2); pxw[i * 384 + 128] = l + h2;
            unpack2(aN[4+i], l, h2); pxw[i * 384 + 256] = l + h2;
        }
        __syncthreads();   // partials exchanged; also: all reads of hs[p] done

        float* hw = hsf + (p ^ 1) * (HSB / 4) + r0 * 132 + u;
        #pragma unroll
        for (int i = 0; i < 4; i++) {
            float rg = sigf(sR[i] + pxr[i * 384 + 0]);
            float zg = sigf(sZ[i] + pxr[i * 384 + 128]);
            float ng = tanhf_fast(cxN[i] + rg * (sN[i] + pxr[i * 384 + 256]));
            hreg[i] = (1.0f - zg) * ng + zg * hreg[i];
            hw[i * 132] = hreg[i];
            cxR[i] = nxR[i]; cxZ[i] = nxZ[i]; cxN[i] = nxN[i];
        }
        __syncthreads();   // new h visible
        p ^= 1;
    }

    // projection: out[b] = sum_u h[b][u]*w_out[u] + b_out (deterministic tree)
    const float wo = w_out[u];
    #pragma unroll
    for (int i = 0; i < 4; i++) red[(r0 + i) * H + u] = hreg[i] * wo;
    __syncthreads();
    for (int st = 64; st > 0; st >>= 1) {
        if (u < st) {
            #pragma unroll
            for (int i = 0; i < 4; i++)
                red[(r0 + i) * H + u] += red[(r0 + i) * H + u + st];
        }
        __syncthreads();
    }
    if (tid < 8) out[b0 + tid] = red[tid * H] + b_out[0];
}

// ---------------------------------------------------------------------------
// launch
// ---------------------------------------------------------------------------
extern "C" void kernel_launch(void* const* d_in, const int* in_sizes, int n_in,
                              void* d_out, int out_size) {
    const float* input     = (const float*)d_in[0];   // [T, B, H]
    const float* initial_h = (const float*)d_in[1];   // [B, H]
    const float* w_ih      = (const float*)d_in[2];   // [3H, H]
    const float* w_hh      = (const float*)d_in[3];   // [3H, H]
    const float* b_ih      = (const float*)d_in[4];   // [3H]
    const float* b_hh      = (const float*)d_in[5];   // [3H]
    const float* w_out     = (const float*)d_in[6];   // [1, H]
    const float* b_out     = (const float*)d_in[7];   // [1]
    float*       out       = (float*)d_out;           // [B, 1]

    (void)in_sizes; (void)n_in; (void)out_size;

    cudaFuncSetAttribute(xg_kernel,  cudaFuncAttributeMaxDynamicSharedMemorySize, SMEM1);
    cudaFuncSetAttribute(gru_kernel, cudaFuncAttributeMaxDynamicSharedMemorySize, SMEM2);

    xg_kernel<<<GRID1, THR1, SMEM1>>>(input, w_ih, b_ih);
    gru_kernel<<<BB / 8, THR2, SMEM2>>>(initial_h, w_hh, b_hh, w_out, b_out, out);
}

// round 10
// speedup vs baseline: 1.1578x; 1.0023x over previous
#include <cuda_runtime.h>
#include <math.h>
#include <stdint.h>

// ---------------------------------------------------------------------------
// GRU: T=512, B=1024, H=128.  out = h_T @ w_out^T + b_out
//
// Phase 1: persistent GEMM, cp.async double-buffered input tiles, FFMA2.
// Phase 2: recurrence with SPLIT-K: 128 units x 2 k-halves per CTA.
//          Every w_hh byte crosses the smem crossbar exactly once per SM per
//          step (no per-warp duplication) -> fma-bound inner loop.
//          Partial sums exchanged through smem once per step (12KB).
// ---------------------------------------------------------------------------

typedef unsigned long long u64;

static __device__ __forceinline__ u64 pack2(float lo, float hi) {
    u64 r; asm("mov.b64 %0, {%1, %2};" : "=l"(r) : "f"(lo), "f"(hi)); return r;
}
static __device__ __forceinline__ void unpack2(u64 v, float& lo, float& hi) {
    asm("mov.b64 {%0, %1}, %2;" : "=f"(lo), "=f"(hi) : "l"(v));
}
static __device__ __forceinline__ u64 ffma2(u64 a, u64 b, u64 c) {
    u64 d; asm("fma.rn.f32x2 %0, %1, %2, %3;" : "=l"(d) : "l"(a), "l"(b), "l"(c)); return d;
}
static __device__ __forceinline__ void lds_v2u64(u64& a, u64& b, uint32_t addr) {
    asm volatile("ld.shared.v2.u64 {%0, %1}, [%2];" : "=l"(a), "=l"(b) : "r"(addr));
}
static __device__ __forceinline__ uint32_t smem_u32(const void* p) {
    uint32_t a;
    asm("{ .reg .u64 t; cvta.to.shared.u64 t, %1; cvt.u32.u64 %0, t; }" : "=r"(a) : "l"(p));
    return a;
}
static __device__ __forceinline__ void cp16(uint32_t dst, const void* src) {
    asm volatile("cp.async.cg.shared.global [%0], [%1], 16;" :: "r"(dst), "l"(src));
}
static __device__ __forceinline__ void cp_commit() {
    asm volatile("cp.async.commit_group;");
}
static __device__ __forceinline__ void cp_wait1() {
    asm volatile("cp.async.wait_group 1;");
}
static __device__ __forceinline__ void cp_wait0() {
    asm volatile("cp.async.wait_group 0;");
}
static __device__ __forceinline__ float sigf(float x) {
    return __fdividef(1.0f, 1.0f + __expf(-x));
}
static __device__ __forceinline__ float tanhf_fast(float x) {
    float ax = fabsf(x);
    float e  = __expf(-2.0f * ax);
    float t  = __fdividef(1.0f - e, 1.0f + e);
    return copysignf(t, x);
}

constexpr int H  = 128;
constexpr int G  = 384;    // 3*H
constexpr int TT = 512;
constexpr int BB = 1024;

// precomputed input gates: [T*B][3H]  (~805 MB static device scratch)
__device__ float g_xg[(size_t)TT * BB * G];

// shared weight tile: ws4[kk][g] (kk = k/4), 32*384*16 B
constexpr int WS_BYTES = 32 * G * 16;      // 196608
constexpr int RP       = 528;              // row pitch in BYTES (132 floats)

// ---------------------------------------------------------------------------
// Phase 1: g_xg = input @ w_ih^T + b_ih   (persistent GEMM, cp.async staging)
// ---------------------------------------------------------------------------
constexpr int ROWS1    = 32;
constexpr int THR1     = 512;
constexpr int NBLK1    = (TT * BB) / ROWS1;   // 16384 tiles
constexpr int GRID1    = 148;
constexpr int XS_BYTES = ROWS1 * RP;          // 16896
constexpr int SMEM1    = WS_BYTES + 2 * XS_BYTES;   // 230400

__global__ void __launch_bounds__(THR1) xg_kernel(const float* __restrict__ input,
                                                  const float* __restrict__ w_ih,
                                                  const float* __restrict__ b_ih) {
    extern __shared__ char smem[];
    float4* ws4 = (float4*)smem;
    const uint32_t ws_a = smem_u32(smem);
    const uint32_t xs_a = ws_a + WS_BYTES;

    const int tid = threadIdx.x;
    const int u   = tid & 127;      // gate unit (gates u, u+128, u+256)
    const int s   = tid >> 7;       // row octet: rows s*8 .. s*8+7

    // stage tile 0 / tile 1 via cp.async while we also stage weights
    const int i0 = tid, i1 = tid + THR1;
    const uint32_t d0 = xs_a + (i0 >> 5) * RP + (i0 & 31) * 16;
    const uint32_t d1 = xs_a + (i1 >> 5) * RP + (i1 & 31) * 16;
    {
        const float4* in4 = (const float4*)(input + (size_t)blockIdx.x * ROWS1 * H);
        cp16(d0, in4 + i0); cp16(d1, in4 + i1); cp_commit();
        const float4* in4b = (const float4*)(input + (size_t)(blockIdx.x + GRID1) * ROWS1 * H);
        cp16(d0 + XS_BYTES, in4b + i0); cp16(d1 + XS_BYTES, in4b + i1); cp_commit();
    }

    // stage weights once: ws4[kk*384 + g] = w_ih[g][4kk..4kk+3]
    const float4* w4 = (const float4*)w_ih;
    for (int i = tid; i < G * 32; i += THR1) {
        int g = i >> 5, kk = i & 31;
        ws4[kk * G + g] = w4[g * 32 + kk];
    }
    const float br = b_ih[u], bz = b_ih[u + 128], bn = b_ih[u + 256];

    const uint32_t wb = ws_a + u * 16;
    int p = 0;

    for (int j = blockIdx.x; j < NBLK1; j += GRID1) {
        cp_wait1();          // buffer p filled
        __syncthreads();     // visible to all (also covers weight staging, 1st iter)

        const uint32_t xb = xs_a + p * XS_BYTES + (s * 8) * RP;

        u64 aR[8], aZ[8], aN[8];
        #pragma unroll
        for (int r = 0; r < 8; r++) {
            aR[r] = pack2(br, 0.f); aZ[r] = pack2(bz, 0.f); aN[r] = pack2(bn, 0.f);
        }

        #pragma unroll 2
        for (int kk = 0; kk < 32; kk++) {
            u64 wr0, wr1, wz0, wz1, wn0, wn1;
            const uint32_t wo = wb + kk * (G * 16);
            lds_v2u64(wr0, wr1, wo);
            lds_v2u64(wz0, wz1, wo + 128 * 16);
            lds_v2u64(wn0, wn1, wo + 256 * 16);
            #pragma unroll
            for (int r = 0; r < 8; r++) {
                u64 x0, x1;
                lds_v2u64(x0, x1, xb + r * RP + kk * 16);   // broadcast
                aR[r] = ffma2(x0, wr0, aR[r]); aR[r] = ffma2(x1, wr1, aR[r]);
                aZ[r] = ffma2(x0, wz0, aZ[r]); aZ[r] = ffma2(x1, wz1, aZ[r]);
                aN[r] = ffma2(x0, wn0, aN[r]); aN[r] = ffma2(x1, wn1, aN[r]);
            }
        }

        float* outp = g_xg + ((size_t)j * ROWS1 + s * 8) * G + u;
        #pragma unroll
        for (int r = 0; r < 8; r++) {
            float l, h2;
            unpack2(aR[r], l, h2); outp[(size_t)r * G]       = l + h2;
            unpack2(aZ[r], l, h2); outp[(size_t)r * G + 128] = l + h2;
            unpack2(aN[r], l, h2); outp[(size_t)r * G + 256] = l + h2;
        }

        __syncthreads();     // everyone done reading buffer p
        int jn = j + 2 * GRID1;
        if (jn < NBLK1) {    // refill buffer p
            const float4* in4 = (const float4*)(input + (size_t)jn * ROWS1 * H);
            cp16(xs_a + p * XS_BYTES + (i0 >> 5) * RP + (i0 & 31) * 16, in4 + i0);
            cp16(xs_a + p * XS_BYTES + (i1 >> 5) * RP + (i1 & 31) * 16, in4 + i1);
        }
        cp_commit();         // commit even if empty (keeps wait accounting)
        p ^= 1;
    }
    cp_wait0();
}

// ---------------------------------------------------------------------------
// Phase 2: split-K recurrence. 128 CTAs x 256 threads.
// thread (u, kh): partial hg over k in [64kh, 64kh+64) for all 8 rows;
// gates + h update for rows [4kh, 4kh+4).
// ---------------------------------------------------------------------------
constexpr int THR2   = 256;
constexpr int HSB    = 8 * RP;                 // 4224 per h buffer
constexpr int PXSIDE = 4 * 3 * 128 * 4;        // 6144 per exchange side
constexpr int SMEM2  = WS_BYTES + 2 * HSB + 2 * PXSIDE + 8 * H * 4;  // 221440

__global__ void __launch_bounds__(THR2) gru_kernel(const float* __restrict__ initial_h,
                                                   const float* __restrict__ w_hh,
                                                   const float* __restrict__ b_hh,
                                                   const float* __restrict__ w_out,
                                                   const float* __restrict__ b_out,
                                                   float* __restrict__ out) {
    extern __shared__ char smem[];
    float4* ws4 = (float4*)smem;
    float*  hsf = (float*)(smem + WS_BYTES);                         // 2 x [8][132]
    float*  pxf = (float*)(smem + WS_BYTES + 2 * HSB);               // 2 x [4][3][128]
    float*  red = (float*)(smem + WS_BYTES + 2 * HSB + 2 * PXSIDE);  // [8][128]
    const uint32_t ws_a = smem_u32(smem);
    const uint32_t hs_a = ws_a + WS_BYTES;

    const int tid = threadIdx.x;
    const int u   = tid & 127;
    const int kh  = tid >> 7;          // k-half
    const int r0  = kh * 4;            // own gate rows: r0 .. r0+3
    const int b0  = blockIdx.x * 8;

    const float4* w4 = (const float4*)w_hh;
    for (int i = tid; i < G * 32; i += THR2) {
        int g = i >> 5, kk = i & 31;
        ws4[kk * G + g] = w4[g * 32 + kk];
    }
    const float br = b_hh[u], bz = b_hh[u + 128], bn = b_hh[u + 256];

    // init h (each half writes its own 4 rows; both halves cover 8)
    float hreg[4];
    #pragma unroll
    for (int i = 0; i < 4; i++) {
        hreg[i] = initial_h[(size_t)(b0 + r0 + i) * H + u];
        hsf[(r0 + i) * 132 + u] = hreg[i];
    }

    // prefetch xg for t = 0 (own rows only)
    float cxR[4], cxZ[4], cxN[4];
    {
        const float* xg0 = g_xg + ((size_t)b0 + r0) * G + u;
        #pragma unroll
        for (int i = 0; i < 4; i++) {
            cxR[i] = xg0[(size_t)i * G];
            cxZ[i] = xg0[(size_t)i * G + 128];
            cxN[i] = xg0[(size_t)i * G + 256];
        }
    }
    __syncthreads();

    // weight base for this (u, k-half); h base includes the k-half byte offset
    const uint32_t wb = ws_a + u * 16 + kh * 16 * (G * 16);
    const int     ro  = 4 - r0;          // other half's first row
    float* pxw = pxf + kh * (4 * 3 * 128) + u;         // write side (our partials)
    float* pxr = pxf + (1 - kh) * (4 * 3 * 128) + u;   // read side (partner's)

    int p = 0;
    for (int t = 0; t < TT; t++) {
        // prefetch next step's xg (own rows)
        float nxR[4], nxZ[4], nxN[4];
        {
            int tn = (t + 1 < TT) ? (t + 1) : t;
            const float* xgn = g_xg + ((size_t)tn * BB + b0 + r0) * G + u;
            #pragma unroll
            for (int i = 0; i < 4; i++) {
                nxR[i] = xgn[(size_t)i * G];
                nxZ[i] = xgn[(size_t)i * G + 128];
                nxN[i] = xgn[(size_t)i * G + 256];
            }
        }

        // accumulators: [0..3] own rows (x+bias folded), [4..7] other rows
        u64 aR[8], aZ[8], aN[8];
        #pragma unroll
        for (int i = 0; i < 4; i++) {
            aR[i] = pack2(cxR[i] + br, 0.f);
            aZ[i] = pack2(cxZ[i] + bz, 0.f);
            aN[i] = pack2(bn, 0.f);
            aR[4 + i] = 0; aZ[4 + i] = 0; aN[4 + i] = 0;
        }

        const uint32_t hb_own = hs_a + p * HSB + r0 * RP + kh * 256;
        const uint32_t hb_oth = hs_a + p * HSB + ro * RP + kh * 256;

        #pragma unroll 2
        for (int kk = 0; kk < 16; kk++) {
            u64 wr0, wr1, wz0, wz1, wn0, wn1;
            const uint32_t wo = wb + kk * (G * 16);
            lds_v2u64(wr0, wr1, wo);
            lds_v2u64(wz0, wz1, wo + 128 * 16);
            lds_v2u64(wn0, wn1, wo + 256 * 16);
            #pragma unroll
            for (int i = 0; i < 4; i++) {
                u64 x0, x1;
                lds_v2u64(x0, x1, hb_own + i * RP + kk * 16);   // broadcast
                aR[i] = ffma2(x0, wr0, aR[i]); aR[i] = ffma2(x1, wr1, aR[i]);
                aZ[i] = ffma2(x0, wz0, aZ[i]); aZ[i] = ffma2(x1, wz1, aZ[i]);
                aN[i] = ffma2(x0, wn0, aN[i]); aN[i] = ffma2(x1, wn1, aN[i]);
            }
            #pragma unroll
            for (int i = 0; i < 4; i++) {
                u64 x0, x1;
                lds_v2u64(x0, x1, hb_oth + i * RP + kk * 16);   // broadcast
                aR[4+i] = ffma2(x0, wr0, aR[4+i]); aR[4+i] = ffma2(x1, wr1, aR[4+i]);
                aZ[4+i] = ffma2(x0, wz0, aZ[4+i]); aZ[4+i] = ffma2(x1, wz1, aZ[4+i]);
                aN[4+i] = ffma2(x0, wn0, aN[4+i]); aN[4+i] = ffma2(x1, wn1, aN[4+i]);
            }
        }

        // fold own sums; export other-rows partials
        float sR[4], sZ[4], sN[4];
        #pragma unroll
        for (int i = 0; i < 4; i++) {
            float l, h2;
            unpack2(aR[i], l, h2); sR[i] = l + h2;
            unpack2(aZ[i], l, h2); sZ[i] = l + h2;
            unpack2(aN[i], l, h2); sN[i] = l + h2;
            unpack2(aR[4+i], l, h2); pxw[i * 384 + 0  ] = l + h2;
            unpack2(aZ[4+i], l, h2); pxw[i * 384 + 128] = l + h2;
            unpack2(aN[4+i], l, h2); pxw[i * 384 + 256] = l + h2;
        }
        __syncthreads();   // partials exchanged; also: all reads of hs[p] done

        float* hw = hsf + (p ^ 1) * (HSB / 4) + r0 * 132 + u;
        #pragma unroll
        for (int i = 0; i < 4; i++) {
            float rg = sigf(sR[i] + pxr[i * 384 + 0]);
            float zg = sigf(sZ[i] + pxr[i * 384 + 128]);
            float ng = tanhf_fast(cxN[i] + rg * (sN[i] + pxr[i * 384 + 256]));
            hreg[i] = (1.0f - zg) * ng + zg * hreg[i];
            hw[i * 132] = hreg[i];
            cxR[i] = nxR[i]; cxZ[i] = nxZ[i]; cxN[i] = nxN[i];
        }
        __syncthreads();   // new h visible
        p ^= 1;
    }

    // projection: out[b] = sum_u h[b][u]*w_out[u] + b_out (deterministic tree)
    const float wo = w_out[u];
    #pragma unroll
    for (int i = 0; i < 4; i++) red[(r0 + i) * H + u] = hreg[i] * wo;
    __syncthreads();
    for (int st = 64; st > 0; st >>= 1) {
        if (u < st) {
            #pragma unroll
            for (int i = 0; i < 4; i++)
                red[(r0 + i) * H + u] += red[(r0 + i) * H + u + st];
        }
        __syncthreads();
    }
    if (tid < 8) out[b0 + tid] = red[tid * H] + b_out[0];
}

// ---------------------------------------------------------------------------
// launch
// ---------------------------------------------------------------------------
extern "C" void kernel_launch(void* const* d_in, const int* in_sizes, int n_in,
                              void* d_out, int out_size) {
    const float* input     = (const float*)d_in[0];   // [T, B, H]
    const float* initial_h = (const float*)d_in[1];   // [B, H]
    const float* w_ih      = (const float*)d_in[2];   // [3H, H]
    const float* w_hh      = (const float*)d_in[3];   // [3H, H]
    const float* b_ih      = (const float*)d_in[4];   // [3H]
    const float* b_hh      = (const float*)d_in[5];   // [3H]
    const float* w_out     = (const float*)d_in[6];   // [1, H]
    const float* b_out     = (const float*)d_in[7];   // [1]
    float*       out       = (float*)d_out;           // [B, 1]

    (void)in_sizes; (void)n_in; (void)out_size;

    cudaFuncSetAttribute(xg_kernel,  cudaFuncAttributeMaxDynamicSharedMemorySize, SMEM1);
    cudaFuncSetAttribute(gru_kernel, cudaFuncAttributeMaxDynamicSharedMemorySize, SMEM2);

    xg_kernel<<<GRID1, THR1, SMEM1>>>(input, w_ih, b_ih);
    gru_kernel<<<BB / 8, THR2, SMEM2>>>(initial_h, w_hh, b_hh, w_out, b_out, out);
}